// round 1
// baseline (speedup 1.0000x reference)
#include <cuda_runtime.h>

#define Bc  4
#define LXc 384
#define LYc 384
#define Hc  256
#define Fc  512

// scratch (allocation-free rule: __device__ globals)
__device__ float g_Xp[Bc * LXc * Hc];   // x @ Wm^T
__device__ float g_Yp[Bc * LYc * Hc];   // y @ Wm^T
__device__ float g_S [Bc * LYc * LXc];  // raw scores

__device__ __forceinline__ float tanh_fast(float x) {
    float r; asm("tanh.approx.f32 %0, %1;" : "=f"(r) : "f"(x)); return r;
}
__device__ __forceinline__ float ex2_fast(float x) {
    float r; asm("ex2.approx.f32 %0, %1;" : "=f"(r) : "f"(x)); return r;
}

// ---------------------------------------------------------------------------
// Kernel 1: Out[r,h] = sum_f In[r,f] * W[h,f]   (NT GEMM, both K-major)
// M=1536, N=256, K=512.  64x64 block tile, BK=16, 4x4 register micro-tile.
// grid.z: 0 -> x->g_Xp, 1 -> y->g_Yp
// ---------------------------------------------------------------------------
__global__ __launch_bounds__(256) void proj_kernel(
    const float* __restrict__ xin, const float* __restrict__ yin,
    const float* __restrict__ W)
{
    const float* In  = blockIdx.z ? yin  : xin;
    float*       Out = blockIdx.z ? g_Yp : g_Xp;

    __shared__ float As[16][68];
    __shared__ float Bs[16][68];

    const int tid  = threadIdx.x;
    const int r0   = blockIdx.x * 64;
    const int h0   = blockIdx.y * 64;
    const int lrow = tid >> 2;          // 0..63
    const int f4   = (tid & 3) * 4;     // 0,4,8,12
    const int tx   = tid & 15;
    const int ty   = tid >> 4;

    float acc[4][4] = {};

    for (int k0 = 0; k0 < Fc; k0 += 16) {
        float4 av = *(const float4*)&In[(r0 + lrow) * Fc + k0 + f4];
        float4 bv = *(const float4*)&W [(h0 + lrow) * Fc + k0 + f4];
        As[f4 + 0][lrow] = av.x; As[f4 + 1][lrow] = av.y;
        As[f4 + 2][lrow] = av.z; As[f4 + 3][lrow] = av.w;
        Bs[f4 + 0][lrow] = bv.x; Bs[f4 + 1][lrow] = bv.y;
        Bs[f4 + 2][lrow] = bv.z; Bs[f4 + 3][lrow] = bv.w;
        __syncthreads();

        #pragma unroll
        for (int kk = 0; kk < 16; kk++) {
            float4 a = *(const float4*)&As[kk][ty * 4];
            float4 b = *(const float4*)&Bs[kk][tx * 4];
            acc[0][0] = fmaf(a.x, b.x, acc[0][0]);
            acc[0][1] = fmaf(a.x, b.y, acc[0][1]);
            acc[0][2] = fmaf(a.x, b.z, acc[0][2]);
            acc[0][3] = fmaf(a.x, b.w, acc[0][3]);
            acc[1][0] = fmaf(a.y, b.x, acc[1][0]);
            acc[1][1] = fmaf(a.y, b.y, acc[1][1]);
            acc[1][2] = fmaf(a.y, b.z, acc[1][2]);
            acc[1][3] = fmaf(a.y, b.w, acc[1][3]);
            acc[2][0] = fmaf(a.z, b.x, acc[2][0]);
            acc[2][1] = fmaf(a.z, b.y, acc[2][1]);
            acc[2][2] = fmaf(a.z, b.z, acc[2][2]);
            acc[2][3] = fmaf(a.z, b.w, acc[2][3]);
            acc[3][0] = fmaf(a.w, b.x, acc[3][0]);
            acc[3][1] = fmaf(a.w, b.y, acc[3][1]);
            acc[3][2] = fmaf(a.w, b.z, acc[3][2]);
            acc[3][3] = fmaf(a.w, b.w, acc[3][3]);
        }
        __syncthreads();
    }

    #pragma unroll
    for (int i = 0; i < 4; i++) {
        float4 st = make_float4(acc[i][0], acc[i][1], acc[i][2], acc[i][3]);
        *(float4*)&Out[(r0 + ty * 4 + i) * Hc + h0 + tx * 4] = st;
    }
}

// ---------------------------------------------------------------------------
// Kernel 2: S[b,y,l] = sum_h vm[h] * tanh(Xp[b,l,h] - Yp[b,y,h])
// 128 threads = 4 warps, warp owns one y row; lane holds 8 h-slots in regs.
// ---------------------------------------------------------------------------
__global__ __launch_bounds__(128) void score_kernel(const float* __restrict__ vm)
{
    const int b    = blockIdx.y;
    const int y    = blockIdx.x * 4 + (threadIdx.x >> 5);
    const int lane = threadIdx.x & 31;

    const float* Yrow = g_Yp + (b * LYc + y) * Hc;
    float yv[8], vr[8];
    #pragma unroll
    for (int k = 0; k < 8; k++) {
        yv[k] = Yrow[lane + 32 * k];
        vr[k] = vm[lane + 32 * k];
    }

    const float* Xb   = g_Xp + b * LXc * Hc;
    float*       Srow = g_S  + (b * LYc + y) * LXc;

    #pragma unroll 2
    for (int l = 0; l < LXc; l++) {
        const float* p = Xb + l * Hc;
        float s = 0.f;
        #pragma unroll
        for (int k = 0; k < 8; k++) {
            float d = p[lane + 32 * k] - yv[k];
            s = fmaf(tanh_fast(d), vr[k], s);
        }
        #pragma unroll
        for (int o = 16; o; o >>= 1)
            s += __shfl_xor_sync(0xffffffffu, s, o);
        if (lane == 0) Srow[l] = s;
    }
}

// ---------------------------------------------------------------------------
// Kernel 3: softmax over l, then qtm[b,y,f] = sum_l a[l] * x[b,l,f]
// block handles 8 y rows; warp-per-row softmax; f split 2 per thread (float2).
// ---------------------------------------------------------------------------
__global__ __launch_bounds__(256) void out_kernel(
    const float* __restrict__ x, float* __restrict__ out)
{
    __shared__ float a_s[8][LXc];

    const int b    = blockIdx.y;
    const int y0   = blockIdx.x * 8;
    const int tid  = threadIdx.x;
    const int w    = tid >> 5;
    const int lane = tid & 31;

    // softmax: warp w handles row y0+w (384 = 32 lanes * 12)
    {
        const float* Srow = g_S + (b * LYc + y0 + w) * LXc;
        float v[12];
        float mx = -1e30f;
        #pragma unroll
        for (int j = 0; j < 12; j++) {
            v[j] = Srow[lane + 32 * j];
            mx = fmaxf(mx, v[j]);
        }
        #pragma unroll
        for (int o = 16; o; o >>= 1)
            mx = fmaxf(mx, __shfl_xor_sync(0xffffffffu, mx, o));
        float sum = 0.f;
        #pragma unroll
        for (int j = 0; j < 12; j++) {
            v[j] = ex2_fast((v[j] - mx) * 1.4426950408889634f);
            sum += v[j];
        }
        #pragma unroll
        for (int o = 16; o; o >>= 1)
            sum += __shfl_xor_sync(0xffffffffu, sum, o);
        float inv = 1.0f / sum;
        #pragma unroll
        for (int j = 0; j < 12; j++)
            a_s[w][lane + 32 * j] = v[j] * inv;
    }
    __syncthreads();

    // weighted sum over l
    const float* xb = x + b * LXc * Fc;
    float2 acc[8];
    #pragma unroll
    for (int t = 0; t < 8; t++) acc[t] = make_float2(0.f, 0.f);
    const int f = tid * 2;

    #pragma unroll 4
    for (int l = 0; l < LXc; l++) {
        float2 xv = *(const float2*)&xb[l * Fc + f];
        #pragma unroll
        for (int t = 0; t < 8; t++) {
            float av = a_s[t][l];
            acc[t].x = fmaf(av, xv.x, acc[t].x);
            acc[t].y = fmaf(av, xv.y, acc[t].y);
        }
    }

    #pragma unroll
    for (int t = 0; t < 8; t++)
        *(float2*)&out[(b * LYc + y0 + t) * Fc + f] = acc[t];
}

// ---------------------------------------------------------------------------
extern "C" void kernel_launch(void* const* d_in, const int* in_sizes, int n_in,
                              void* d_out, int out_size)
{
    const float* x  = (const float*)d_in[0];
    const float* y  = (const float*)d_in[1];
    const float* Wm = (const float*)d_in[2];
    const float* vm = (const float*)d_in[3];
    float* out = (float*)d_out;

    proj_kernel <<<dim3(LXc * Bc / 64, Hc / 64, 2), 256>>>(x, y, Wm);
    score_kernel<<<dim3(LYc / 4, Bc), 128>>>(vm);
    out_kernel  <<<dim3(LYc / 8, Bc), 256>>>(x, out);
}

// round 2
// speedup vs baseline: 2.9218x; 2.9218x over previous
#include <cuda_runtime.h>

#define Bc  4
#define LXc 384
#define LYc 384
#define Hc  256
#define Fc  512

// scratch (allocation-free rule: __device__ globals)
__device__ float g_Xp[Bc * LXc * Hc];   // x @ Wm^T
__device__ float g_Yp[Bc * LYc * Hc];   // y @ Wm^T
__device__ float g_S [Bc * LYc * LXc];  // raw scores

__device__ __forceinline__ float tanh_fast(float x) {
    float r; asm("tanh.approx.f32 %0, %1;" : "=f"(r) : "f"(x)); return r;
}
__device__ __forceinline__ float ex2_fast(float x) {
    float r; asm("ex2.approx.f32 %0, %1;" : "=f"(r) : "f"(x)); return r;
}

// ---------------------------------------------------------------------------
// Kernel 1: Out[r,h] = sum_f In[r,f] * W[h,f]   (NT GEMM, both K-major)
// M=1536, N=256, K=512.  64x64 block tile, BK=16, 4x4 register micro-tile.
// grid.z: 0 -> x->g_Xp, 1 -> y->g_Yp
// ---------------------------------------------------------------------------
__global__ __launch_bounds__(256) void proj_kernel(
    const float* __restrict__ xin, const float* __restrict__ yin,
    const float* __restrict__ W)
{
    const float* In  = blockIdx.z ? yin  : xin;
    float*       Out = blockIdx.z ? g_Yp : g_Xp;

    __shared__ float As[16][68];
    __shared__ float Bs[16][68];

    const int tid  = threadIdx.x;
    const int r0   = blockIdx.x * 64;
    const int h0   = blockIdx.y * 64;
    const int lrow = tid >> 2;          // 0..63
    const int f4   = (tid & 3) * 4;     // 0,4,8,12
    const int tx   = tid & 15;
    const int ty   = tid >> 4;

    float acc[4][4] = {};

    for (int k0 = 0; k0 < Fc; k0 += 16) {
        float4 av = *(const float4*)&In[(r0 + lrow) * Fc + k0 + f4];
        float4 bv = *(const float4*)&W [(h0 + lrow) * Fc + k0 + f4];
        As[f4 + 0][lrow] = av.x; As[f4 + 1][lrow] = av.y;
        As[f4 + 2][lrow] = av.z; As[f4 + 3][lrow] = av.w;
        Bs[f4 + 0][lrow] = bv.x; Bs[f4 + 1][lrow] = bv.y;
        Bs[f4 + 2][lrow] = bv.z; Bs[f4 + 3][lrow] = bv.w;
        __syncthreads();

        #pragma unroll
        for (int kk = 0; kk < 16; kk++) {
            float4 a = *(const float4*)&As[kk][ty * 4];
            float4 b = *(const float4*)&Bs[kk][tx * 4];
            acc[0][0] = fmaf(a.x, b.x, acc[0][0]);
            acc[0][1] = fmaf(a.x, b.y, acc[0][1]);
            acc[0][2] = fmaf(a.x, b.z, acc[0][2]);
            acc[0][3] = fmaf(a.x, b.w, acc[0][3]);
            acc[1][0] = fmaf(a.y, b.x, acc[1][0]);
            acc[1][1] = fmaf(a.y, b.y, acc[1][1]);
            acc[1][2] = fmaf(a.y, b.z, acc[1][2]);
            acc[1][3] = fmaf(a.y, b.w, acc[1][3]);
            acc[2][0] = fmaf(a.z, b.x, acc[2][0]);
            acc[2][1] = fmaf(a.z, b.y, acc[2][1]);
            acc[2][2] = fmaf(a.z, b.z, acc[2][2]);
            acc[2][3] = fmaf(a.z, b.w, acc[2][3]);
            acc[3][0] = fmaf(a.w, b.x, acc[3][0]);
            acc[3][1] = fmaf(a.w, b.y, acc[3][1]);
            acc[3][2] = fmaf(a.w, b.z, acc[3][2]);
            acc[3][3] = fmaf(a.w, b.w, acc[3][3]);
        }
        __syncthreads();
    }

    #pragma unroll
    for (int i = 0; i < 4; i++) {
        float4 st = make_float4(acc[i][0], acc[i][1], acc[i][2], acc[i][3]);
        *(float4*)&Out[(r0 + ty * 4 + i) * Hc + h0 + tx * 4] = st;
    }
}

// ---------------------------------------------------------------------------
// Kernel 2 (NEW): GEMM-shaped tanh-score.
// S[b,y,l] = sum_h vm[h] * tanh(Xp[b,l,h] - Yp[b,y,h])
// Block computes a 64(y) x 64(l) tile; k-chunks of 16 through smem;
// 4x4 register micro-tile. MUFU(tanh)-bound by design: per kk-step a thread
// issues 16 independent tanh (rt 8/SMSP) vs ~64 cyc of fadd/ffma.
// Grid 6*6*4 = 144 blocks = one wave on 148 SMs.
// ---------------------------------------------------------------------------
__global__ __launch_bounds__(256) void score_tile_kernel(const float* __restrict__ vm)
{
    const int b  = blockIdx.z;
    const int y0 = blockIdx.y * 64;
    const int l0 = blockIdx.x * 64;

    __shared__ float Ys[16][68];   // [k][y]
    __shared__ float Xs[16][68];   // [k][l]
    __shared__ float Vs[Hc];

    const int tid = threadIdx.x;
    for (int i = tid; i < Hc; i += 256) Vs[i] = vm[i];

    const int lrow = tid >> 2;          // 0..63
    const int f4   = (tid & 3) * 4;     // 0,4,8,12
    const int tx   = tid & 15;          // l micro-col
    const int ty   = tid >> 4;          // y micro-row

    const float* Yb = g_Yp + (b * LYc + y0) * Hc;
    const float* Xb = g_Xp + (b * LXc + l0) * Hc;

    float acc[4][4] = {};

    for (int k0 = 0; k0 < Hc; k0 += 16) {
        float4 av = *(const float4*)&Yb[lrow * Hc + k0 + f4];
        float4 bv = *(const float4*)&Xb[lrow * Hc + k0 + f4];
        __syncthreads();   // previous compute done before smem overwrite
        Ys[f4 + 0][lrow] = av.x; Ys[f4 + 1][lrow] = av.y;
        Ys[f4 + 2][lrow] = av.z; Ys[f4 + 3][lrow] = av.w;
        Xs[f4 + 0][lrow] = bv.x; Xs[f4 + 1][lrow] = bv.y;
        Xs[f4 + 2][lrow] = bv.z; Xs[f4 + 3][lrow] = bv.w;
        __syncthreads();

        #pragma unroll
        for (int kk = 0; kk < 16; kk++) {
            const float v = Vs[k0 + kk];
            float4 yv = *(const float4*)&Ys[kk][ty * 4];
            float4 xv = *(const float4*)&Xs[kk][tx * 4];
            float t00 = tanh_fast(xv.x - yv.x);
            float t01 = tanh_fast(xv.y - yv.x);
            float t02 = tanh_fast(xv.z - yv.x);
            float t03 = tanh_fast(xv.w - yv.x);
            float t10 = tanh_fast(xv.x - yv.y);
            float t11 = tanh_fast(xv.y - yv.y);
            float t12 = tanh_fast(xv.z - yv.y);
            float t13 = tanh_fast(xv.w - yv.y);
            float t20 = tanh_fast(xv.x - yv.z);
            float t21 = tanh_fast(xv.y - yv.z);
            float t22 = tanh_fast(xv.z - yv.z);
            float t23 = tanh_fast(xv.w - yv.z);
            float t30 = tanh_fast(xv.x - yv.w);
            float t31 = tanh_fast(xv.y - yv.w);
            float t32 = tanh_fast(xv.z - yv.w);
            float t33 = tanh_fast(xv.w - yv.w);
            acc[0][0] = fmaf(v, t00, acc[0][0]);
            acc[0][1] = fmaf(v, t01, acc[0][1]);
            acc[0][2] = fmaf(v, t02, acc[0][2]);
            acc[0][3] = fmaf(v, t03, acc[0][3]);
            acc[1][0] = fmaf(v, t10, acc[1][0]);
            acc[1][1] = fmaf(v, t11, acc[1][1]);
            acc[1][2] = fmaf(v, t12, acc[1][2]);
            acc[1][3] = fmaf(v, t13, acc[1][3]);
            acc[2][0] = fmaf(v, t20, acc[2][0]);
            acc[2][1] = fmaf(v, t21, acc[2][1]);
            acc[2][2] = fmaf(v, t22, acc[2][2]);
            acc[2][3] = fmaf(v, t23, acc[2][3]);
            acc[3][0] = fmaf(v, t30, acc[3][0]);
            acc[3][1] = fmaf(v, t31, acc[3][1]);
            acc[3][2] = fmaf(v, t32, acc[3][2]);
            acc[3][3] = fmaf(v, t33, acc[3][3]);
        }
    }

    float* Sb = g_S + (b * LYc + y0) * LXc + l0;
    #pragma unroll
    for (int i = 0; i < 4; i++) {
        float4 st = make_float4(acc[i][0], acc[i][1], acc[i][2], acc[i][3]);
        *(float4*)&Sb[(ty * 4 + i) * LXc + tx * 4] = st;
    }
}

// ---------------------------------------------------------------------------
// Kernel 3: softmax over l, then qtm[b,y,f] = sum_l a[l] * x[b,l,f]
// block handles 8 y rows; warp-per-row softmax; f split 2 per thread (float2).
// ---------------------------------------------------------------------------
__global__ __launch_bounds__(256) void out_kernel(
    const float* __restrict__ x, float* __restrict__ out)
{
    __shared__ float a_s[8][LXc];

    const int b    = blockIdx.y;
    const int y0   = blockIdx.x * 8;
    const int tid  = threadIdx.x;
    const int w    = tid >> 5;
    const int lane = tid & 31;

    // softmax: warp w handles row y0+w (384 = 32 lanes * 12)
    {
        const float* Srow = g_S + (b * LYc + y0 + w) * LXc;
        float v[12];
        float mx = -1e30f;
        #pragma unroll
        for (int j = 0; j < 12; j++) {
            v[j] = Srow[lane + 32 * j];
            mx = fmaxf(mx, v[j]);
        }
        #pragma unroll
        for (int o = 16; o; o >>= 1)
            mx = fmaxf(mx, __shfl_xor_sync(0xffffffffu, mx, o));
        float sum = 0.f;
        #pragma unroll
        for (int j = 0; j < 12; j++) {
            v[j] = ex2_fast((v[j] - mx) * 1.4426950408889634f);
            sum += v[j];
        }
        #pragma unroll
        for (int o = 16; o; o >>= 1)
            sum += __shfl_xor_sync(0xffffffffu, sum, o);
        float inv = 1.0f / sum;
        #pragma unroll
        for (int j = 0; j < 12; j++)
            a_s[w][lane + 32 * j] = v[j] * inv;
    }
    __syncthreads();

    // weighted sum over l
    const float* xb = x + b * LXc * Fc;
    float2 acc[8];
    #pragma unroll
    for (int t = 0; t < 8; t++) acc[t] = make_float2(0.f, 0.f);
    const int f = tid * 2;

    #pragma unroll 4
    for (int l = 0; l < LXc; l++) {
        float2 xv = *(const float2*)&xb[l * Fc + f];
        #pragma unroll
        for (int t = 0; t < 8; t++) {
            float av = a_s[t][l];
            acc[t].x = fmaf(av, xv.x, acc[t].x);
            acc[t].y = fmaf(av, xv.y, acc[t].y);
        }
    }

    #pragma unroll
    for (int t = 0; t < 8; t++)
        *(float2*)&out[(b * LYc + y0 + t) * Fc + f] = acc[t];
}

// ---------------------------------------------------------------------------
extern "C" void kernel_launch(void* const* d_in, const int* in_sizes, int n_in,
                              void* d_out, int out_size)
{
    const float* x  = (const float*)d_in[0];
    const float* y  = (const float*)d_in[1];
    const float* Wm = (const float*)d_in[2];
    const float* vm = (const float*)d_in[3];
    float* out = (float*)d_out;

    proj_kernel      <<<dim3(LXc * Bc / 64, Hc / 64, 2), 256>>>(x, y, Wm);
    score_tile_kernel<<<dim3(LXc / 64, LYc / 64, Bc), 256>>>(vm);
    out_kernel       <<<dim3(LYc / 8, Bc), 256>>>(x, out);
}

// round 3
// speedup vs baseline: 3.0734x; 1.0519x over previous
#include <cuda_runtime.h>

#define Bc  4
#define LXc 384
#define LYc 384
#define Hc  256
#define Fc  512

typedef unsigned long long ull;

// scratch (allocation-free rule: __device__ globals)
__device__ float g_Xp[Bc * LXc * Hc];   // x @ Wm^T
__device__ float g_Yp[Bc * LYc * Hc];   // y @ Wm^T
__device__ float g_S [Bc * LYc * LXc];  // scores -> softmax'd in place

__device__ __forceinline__ float tanh_fast(float x) {
    float r; asm("tanh.approx.f32 %0, %1;" : "=f"(r) : "f"(x)); return r;
}
__device__ __forceinline__ float ex2_fast(float x) {
    float r; asm("ex2.approx.f32 %0, %1;" : "=f"(r) : "f"(x)); return r;
}
__device__ __forceinline__ ull pack2(float lo, float hi) {
    ull r; asm("mov.b64 %0, {%1, %2};" : "=l"(r) : "f"(lo), "f"(hi)); return r;
}
__device__ __forceinline__ float2 unpack2(ull v) {
    float lo, hi; asm("mov.b64 {%0, %1}, %2;" : "=f"(lo), "=f"(hi) : "l"(v));
    return make_float2(lo, hi);
}
__device__ __forceinline__ ull fma2(ull a, ull b, ull c) {
    ull r; asm("fma.rn.f32x2 %0, %1, %2, %3;" : "=l"(r) : "l"(a), "l"(b), "l"(c));
    return r;
}

// ---------------------------------------------------------------------------
// Kernel 1: Out[r,h] = sum_f In[r,f] * W[h,f]   (NT GEMM, both K-major)
// M=1536, N=256, K=512. 64x64 tile, BK=16, double-buffered smem,
// register prefetch, packed fma.rn.f32x2 (FFMA2) micro-kernel.
// ---------------------------------------------------------------------------
__global__ __launch_bounds__(256) void proj_kernel(
    const float* __restrict__ xin, const float* __restrict__ yin,
    const float* __restrict__ W)
{
    const float* In  = blockIdx.z ? yin  : xin;
    float*       Out = blockIdx.z ? g_Yp : g_Xp;

    __shared__ float As[2][16][68];
    __shared__ float Bs[2][16][68];

    const int tid  = threadIdx.x;
    const int r0   = blockIdx.x * 64;
    const int h0   = blockIdx.y * 64;
    const int lrow = tid >> 2;          // 0..63
    const int f4   = (tid & 3) * 4;     // 0,4,8,12
    const int tx   = tid & 15;
    const int ty   = tid >> 4;

    const float* pIn = &In[(r0 + lrow) * Fc + f4];
    const float* pW  = &W [(h0 + lrow) * Fc + f4];

    ull acc[4][2] = {};

    // prologue: chunk 0 -> buf 0
    {
        float4 av = *(const float4*)pIn;
        float4 bv = *(const float4*)pW;
        As[0][f4 + 0][lrow] = av.x; As[0][f4 + 1][lrow] = av.y;
        As[0][f4 + 2][lrow] = av.z; As[0][f4 + 3][lrow] = av.w;
        Bs[0][f4 + 0][lrow] = bv.x; Bs[0][f4 + 1][lrow] = bv.y;
        Bs[0][f4 + 2][lrow] = bv.z; Bs[0][f4 + 3][lrow] = bv.w;
    }
    __syncthreads();

    int buf = 0;
    for (int k0 = 16; k0 <= Fc; k0 += 16) {
        float4 av, bv;
        if (k0 < Fc) {                       // prefetch next chunk
            av = *(const float4*)(pIn + k0);
            bv = *(const float4*)(pW  + k0);
        }
        #pragma unroll
        for (int kk = 0; kk < 16; kk++) {
            float4 a  = *(const float4*)&As[buf][kk][ty * 4];
            ull b01   = *(const ull*)&Bs[buf][kk][tx * 4];
            ull b23   = *(const ull*)&Bs[buf][kk][tx * 4 + 2];
            ull ax = pack2(a.x, a.x), ay = pack2(a.y, a.y);
            ull az = pack2(a.z, a.z), aw = pack2(a.w, a.w);
            acc[0][0] = fma2(ax, b01, acc[0][0]);
            acc[0][1] = fma2(ax, b23, acc[0][1]);
            acc[1][0] = fma2(ay, b01, acc[1][0]);
            acc[1][1] = fma2(ay, b23, acc[1][1]);
            acc[2][0] = fma2(az, b01, acc[2][0]);
            acc[2][1] = fma2(az, b23, acc[2][1]);
            acc[3][0] = fma2(aw, b01, acc[3][0]);
            acc[3][1] = fma2(aw, b23, acc[3][1]);
        }
        if (k0 < Fc) {
            int nb = buf ^ 1;
            As[nb][f4 + 0][lrow] = av.x; As[nb][f4 + 1][lrow] = av.y;
            As[nb][f4 + 2][lrow] = av.z; As[nb][f4 + 3][lrow] = av.w;
            Bs[nb][f4 + 0][lrow] = bv.x; Bs[nb][f4 + 1][lrow] = bv.y;
            Bs[nb][f4 + 2][lrow] = bv.z; Bs[nb][f4 + 3][lrow] = bv.w;
            __syncthreads();
            buf = nb;
        }
    }

    #pragma unroll
    for (int i = 0; i < 4; i++) {
        float2 p0 = unpack2(acc[i][0]);
        float2 p1 = unpack2(acc[i][1]);
        *(float4*)&Out[(r0 + ty * 4 + i) * Hc + h0 + tx * 4] =
            make_float4(p0.x, p0.y, p1.x, p1.y);
    }
}

// ---------------------------------------------------------------------------
// Kernel 2: GEMM-shaped tanh-score (MUFU-bound, at its floor — unchanged).
// S[b,y,l] = sum_h vm[h] * tanh(Xp[b,l,h] - Yp[b,y,h])
// ---------------------------------------------------------------------------
__global__ __launch_bounds__(256) void score_tile_kernel(const float* __restrict__ vm)
{
    const int b  = blockIdx.z;
    const int y0 = blockIdx.y * 64;
    const int l0 = blockIdx.x * 64;

    __shared__ float Ys[16][68];
    __shared__ float Xs[16][68];
    __shared__ float Vs[Hc];

    const int tid = threadIdx.x;
    for (int i = tid; i < Hc; i += 256) Vs[i] = vm[i];

    const int lrow = tid >> 2;
    const int f4   = (tid & 3) * 4;
    const int tx   = tid & 15;
    const int ty   = tid >> 4;

    const float* Yb = g_Yp + (b * LYc + y0) * Hc;
    const float* Xb = g_Xp + (b * LXc + l0) * Hc;

    float acc[4][4] = {};

    for (int k0 = 0; k0 < Hc; k0 += 16) {
        float4 av = *(const float4*)&Yb[lrow * Hc + k0 + f4];
        float4 bv = *(const float4*)&Xb[lrow * Hc + k0 + f4];
        __syncthreads();
        Ys[f4 + 0][lrow] = av.x; Ys[f4 + 1][lrow] = av.y;
        Ys[f4 + 2][lrow] = av.z; Ys[f4 + 3][lrow] = av.w;
        Xs[f4 + 0][lrow] = bv.x; Xs[f4 + 1][lrow] = bv.y;
        Xs[f4 + 2][lrow] = bv.z; Xs[f4 + 3][lrow] = bv.w;
        __syncthreads();

        #pragma unroll
        for (int kk = 0; kk < 16; kk++) {
            const float v = Vs[k0 + kk];
            float4 yv = *(const float4*)&Ys[kk][ty * 4];
            float4 xv = *(const float4*)&Xs[kk][tx * 4];
            float t00 = tanh_fast(xv.x - yv.x);
            float t01 = tanh_fast(xv.y - yv.x);
            float t02 = tanh_fast(xv.z - yv.x);
            float t03 = tanh_fast(xv.w - yv.x);
            float t10 = tanh_fast(xv.x - yv.y);
            float t11 = tanh_fast(xv.y - yv.y);
            float t12 = tanh_fast(xv.z - yv.y);
            float t13 = tanh_fast(xv.w - yv.y);
            float t20 = tanh_fast(xv.x - yv.z);
            float t21 = tanh_fast(xv.y - yv.z);
            float t22 = tanh_fast(xv.z - yv.z);
            float t23 = tanh_fast(xv.w - yv.z);
            float t30 = tanh_fast(xv.x - yv.w);
            float t31 = tanh_fast(xv.y - yv.w);
            float t32 = tanh_fast(xv.z - yv.w);
            float t33 = tanh_fast(xv.w - yv.w);
            acc[0][0] = fmaf(v, t00, acc[0][0]);
            acc[0][1] = fmaf(v, t01, acc[0][1]);
            acc[0][2] = fmaf(v, t02, acc[0][2]);
            acc[0][3] = fmaf(v, t03, acc[0][3]);
            acc[1][0] = fmaf(v, t10, acc[1][0]);
            acc[1][1] = fmaf(v, t11, acc[1][1]);
            acc[1][2] = fmaf(v, t12, acc[1][2]);
            acc[1][3] = fmaf(v, t13, acc[1][3]);
            acc[2][0] = fmaf(v, t20, acc[2][0]);
            acc[2][1] = fmaf(v, t21, acc[2][1]);
            acc[2][2] = fmaf(v, t22, acc[2][2]);
            acc[2][3] = fmaf(v, t23, acc[2][3]);
            acc[3][0] = fmaf(v, t30, acc[3][0]);
            acc[3][1] = fmaf(v, t31, acc[3][1]);
            acc[3][2] = fmaf(v, t32, acc[3][2]);
            acc[3][3] = fmaf(v, t33, acc[3][3]);
        }
    }

    float* Sb = g_S + (b * LYc + y0) * LXc + l0;
    #pragma unroll
    for (int i = 0; i < 4; i++) {
        float4 st = make_float4(acc[i][0], acc[i][1], acc[i][2], acc[i][3]);
        *(float4*)&Sb[(ty * 4 + i) * LXc + tx * 4] = st;
    }
}

// ---------------------------------------------------------------------------
// Kernel 3a: softmax over l, in place on g_S. Warp per row.
// ---------------------------------------------------------------------------
__global__ __launch_bounds__(256) void softmax_kernel()
{
    const int b    = blockIdx.y;
    const int y    = blockIdx.x * 8 + (threadIdx.x >> 5);
    const int lane = threadIdx.x & 31;

    float* Srow = g_S + (b * LYc + y) * LXc;
    float v[12];
    float mx = -1e30f;
    #pragma unroll
    for (int j = 0; j < 12; j++) {
        v[j] = Srow[lane + 32 * j];
        mx = fmaxf(mx, v[j]);
    }
    #pragma unroll
    for (int o = 16; o; o >>= 1)
        mx = fmaxf(mx, __shfl_xor_sync(0xffffffffu, mx, o));
    float sum = 0.f;
    #pragma unroll
    for (int j = 0; j < 12; j++) {
        v[j] = ex2_fast((v[j] - mx) * 1.4426950408889634f);
        sum += v[j];
    }
    #pragma unroll
    for (int o = 16; o; o >>= 1)
        sum += __shfl_xor_sync(0xffffffffu, sum, o);
    float inv = 1.0f / sum;
    #pragma unroll
    for (int j = 0; j < 12; j++)
        Srow[lane + 32 * j] = v[j] * inv;
}

// ---------------------------------------------------------------------------
// Kernel 3b: qtm[b,y,f] = sum_l A[b,y,l] * x[b,l,f]
// Per batch GEMM M=384, N=512, K=384. 64x64 tile, BK=16, double-buffered,
// FFMA2 micro-kernel. grid (8, 6, 4) = 192 blocks.
// ---------------------------------------------------------------------------
__global__ __launch_bounds__(256) void outgemm_kernel(
    const float* __restrict__ x, float* __restrict__ out)
{
    const int b  = blockIdx.z;
    const int f0 = blockIdx.x * 64;
    const int y0 = blockIdx.y * 64;

    __shared__ float As[2][16][68];   // [k(l)][y]
    __shared__ float Xs[2][16][68];   // [k(l)][f]

    const int tid  = threadIdx.x;
    const int lrow = tid >> 2;          // y row for A load
    const int f4   = (tid & 3) * 4;     // l sub for A load
    const int lx   = tid >> 4;          // l row for X load
    const int fx   = (tid & 15) * 4;    // f sub for X load
    const int tx   = tid & 15;
    const int ty   = tid >> 4;

    const float* pA = g_S + (b * LYc + y0 + lrow) * LXc + f4;
    const float* pX = x + b * LXc * Fc + lx * Fc + f0 + fx;

    ull acc[4][2] = {};

    {
        float4 av = *(const float4*)pA;
        float4 xv = *(const float4*)pX;
        As[0][f4 + 0][lrow] = av.x; As[0][f4 + 1][lrow] = av.y;
        As[0][f4 + 2][lrow] = av.z; As[0][f4 + 3][lrow] = av.w;
        *(float4*)&Xs[0][lx][fx] = xv;
    }
    __syncthreads();

    int buf = 0;
    for (int k0 = 16; k0 <= LXc; k0 += 16) {
        float4 av, xv;
        if (k0 < LXc) {
            av = *(const float4*)(pA + k0);
            xv = *(const float4*)(pX + k0 * Fc);
        }
        #pragma unroll
        for (int kk = 0; kk < 16; kk++) {
            float4 a  = *(const float4*)&As[buf][kk][ty * 4];
            ull b01   = *(const ull*)&Xs[buf][kk][tx * 4];
            ull b23   = *(const ull*)&Xs[buf][kk][tx * 4 + 2];
            ull ax = pack2(a.x, a.x), ay = pack2(a.y, a.y);
            ull az = pack2(a.z, a.z), aw = pack2(a.w, a.w);
            acc[0][0] = fma2(ax, b01, acc[0][0]);
            acc[0][1] = fma2(ax, b23, acc[0][1]);
            acc[1][0] = fma2(ay, b01, acc[1][0]);
            acc[1][1] = fma2(ay, b23, acc[1][1]);
            acc[2][0] = fma2(az, b01, acc[2][0]);
            acc[2][1] = fma2(az, b23, acc[2][1]);
            acc[3][0] = fma2(aw, b01, acc[3][0]);
            acc[3][1] = fma2(aw, b23, acc[3][1]);
        }
        if (k0 < LXc) {
            int nb = buf ^ 1;
            As[nb][f4 + 0][lrow] = av.x; As[nb][f4 + 1][lrow] = av.y;
            As[nb][f4 + 2][lrow] = av.z; As[nb][f4 + 3][lrow] = av.w;
            *(float4*)&Xs[nb][lx][fx] = xv;
            __syncthreads();
            buf = nb;
        }
    }

    #pragma unroll
    for (int i = 0; i < 4; i++) {
        float2 p0 = unpack2(acc[i][0]);
        float2 p1 = unpack2(acc[i][1]);
        *(float4*)&out[(b * LYc + y0 + ty * 4 + i) * Fc + f0 + tx * 4] =
            make_float4(p0.x, p0.y, p1.x, p1.y);
    }
}

// ---------------------------------------------------------------------------
extern "C" void kernel_launch(void* const* d_in, const int* in_sizes, int n_in,
                              void* d_out, int out_size)
{
    const float* x  = (const float*)d_in[0];
    const float* y  = (const float*)d_in[1];
    const float* Wm = (const float*)d_in[2];
    const float* vm = (const float*)d_in[3];
    float* out = (float*)d_out;

    proj_kernel      <<<dim3(LXc * Bc / 64, Hc / 64, 2), 256>>>(x, y, Wm);
    score_tile_kernel<<<dim3(LXc / 64, LYc / 64, Bc), 256>>>(vm);
    softmax_kernel   <<<dim3(LYc / 8, Bc), 256>>>();
    outgemm_kernel   <<<dim3(Fc / 64, LYc / 64, Bc), 256>>>(x, out);
}

// round 5
// speedup vs baseline: 3.2702x; 1.0640x over previous
#include <cuda_runtime.h>

#define Bc  4
#define LXc 384
#define LYc 384
#define Hc  256
#define Fc  512

typedef unsigned long long ull;

// scratch (allocation-free rule: __device__ globals)
__device__ float g_Xp[Bc * LXc * Hc];   // x @ Wm^T
__device__ float g_Yp[Bc * LYc * Hc];   // y @ Wm^T
__device__ float g_S [Bc * LYc * LXc];  // scores -> softmax'd in place

__device__ __forceinline__ float tanh_fast(float x) {
    float r; asm("tanh.approx.f32 %0, %1;" : "=f"(r) : "f"(x)); return r;
}
__device__ __forceinline__ float ex2_fast(float x) {
    float r; asm("ex2.approx.f32 %0, %1;" : "=f"(r) : "f"(x)); return r;
}
__device__ __forceinline__ ull pack2(float lo, float hi) {
    ull r; asm("mov.b64 %0, {%1, %2};" : "=l"(r) : "f"(lo), "f"(hi)); return r;
}
__device__ __forceinline__ float2 unpack2(ull v) {
    float lo, hi; asm("mov.b64 {%0, %1}, %2;" : "=f"(lo), "=f"(hi) : "l"(v));
    return make_float2(lo, hi);
}
__device__ __forceinline__ ull fma2(ull a, ull b, ull c) {
    ull r; asm("fma.rn.f32x2 %0, %1, %2, %3;" : "=l"(r) : "l"(a), "l"(b), "l"(c));
    return r;
}

// ---------------------------------------------------------------------------
// Kernel 1: Out[r,h] = sum_f In[r,f] * W[h,f]   (NT GEMM, both K-major)
// M=1536, N=256, K=512.  32x64 tile, 128 threads, BK=16 double-buffered,
// FFMA2 micro-kernel.  grid (48, 4, 2) = 384 blocks -> ~2.6 blocks/SM.
// Padding: A rows 36 floats (144B, 16-aligned), B rows 68 (272B, 16-aligned).
// ---------------------------------------------------------------------------
__global__ __launch_bounds__(128) void proj_kernel(
    const float* __restrict__ xin, const float* __restrict__ yin,
    const float* __restrict__ W)
{
    const float* In  = blockIdx.z ? yin  : xin;
    float*       Out = blockIdx.z ? g_Yp : g_Xp;

    __shared__ float As[2][16][36];   // [k][m(32)]
    __shared__ float Bs[2][16][68];   // [k][n(64)]

    const int tid  = threadIdx.x;
    const int r0   = blockIdx.x * 32;
    const int h0   = blockIdx.y * 64;

    const int lrA = tid >> 2;           // 0..31  (m row for A load)
    const int kA  = (tid & 3) * 4;      // k sub for A load
    const int lrB = tid >> 1;           // 0..63  (n row for B load)
    const int kB  = (tid & 1) * 8;      // k sub for B load (8 floats)

    const int tx = tid & 15;            // n micro-col
    const int ty = tid >> 4;            // m micro-row (0..7)

    const float* pA = &In[(r0 + lrA) * Fc + kA];
    const float* pB = &W [(h0 + lrB) * Fc + kB];

    ull acc[4][2] = {};

    // prologue: chunk 0 -> buf 0
    {
        float4 av  = *(const float4*)pA;
        float4 bv0 = *(const float4*)pB;
        float4 bv1 = *(const float4*)(pB + 4);
        As[0][kA + 0][lrA] = av.x;  As[0][kA + 1][lrA] = av.y;
        As[0][kA + 2][lrA] = av.z;  As[0][kA + 3][lrA] = av.w;
        Bs[0][kB + 0][lrB] = bv0.x; Bs[0][kB + 1][lrB] = bv0.y;
        Bs[0][kB + 2][lrB] = bv0.z; Bs[0][kB + 3][lrB] = bv0.w;
        Bs[0][kB + 4][lrB] = bv1.x; Bs[0][kB + 5][lrB] = bv1.y;
        Bs[0][kB + 6][lrB] = bv1.z; Bs[0][kB + 7][lrB] = bv1.w;
    }
    __syncthreads();

    int buf = 0;
    for (int k0 = 16; k0 <= Fc; k0 += 16) {
        float4 av, bv0, bv1;
        if (k0 < Fc) {
            av  = *(const float4*)(pA + k0);
            bv0 = *(const float4*)(pB + k0);
            bv1 = *(const float4*)(pB + k0 + 4);
        }
        #pragma unroll
        for (int kk = 0; kk < 16; kk++) {
            float4 a = *(const float4*)&As[buf][kk][ty * 4];
            ull b01  = *(const ull*)&Bs[buf][kk][tx * 4];
            ull b23  = *(const ull*)&Bs[buf][kk][tx * 4 + 2];
            ull ax = pack2(a.x, a.x), ay = pack2(a.y, a.y);
            ull az = pack2(a.z, a.z), aw = pack2(a.w, a.w);
            acc[0][0] = fma2(ax, b01, acc[0][0]);
            acc[0][1] = fma2(ax, b23, acc[0][1]);
            acc[1][0] = fma2(ay, b01, acc[1][0]);
            acc[1][1] = fma2(ay, b23, acc[1][1]);
            acc[2][0] = fma2(az, b01, acc[2][0]);
            acc[2][1] = fma2(az, b23, acc[2][1]);
            acc[3][0] = fma2(aw, b01, acc[3][0]);
            acc[3][1] = fma2(aw, b23, acc[3][1]);
        }
        if (k0 < Fc) {
            int nb = buf ^ 1;
            As[nb][kA + 0][lrA] = av.x;  As[nb][kA + 1][lrA] = av.y;
            As[nb][kA + 2][lrA] = av.z;  As[nb][kA + 3][lrA] = av.w;
            Bs[nb][kB + 0][lrB] = bv0.x; Bs[nb][kB + 1][lrB] = bv0.y;
            Bs[nb][kB + 2][lrB] = bv0.z; Bs[nb][kB + 3][lrB] = bv0.w;
            Bs[nb][kB + 4][lrB] = bv1.x; Bs[nb][kB + 5][lrB] = bv1.y;
            Bs[nb][kB + 6][lrB] = bv1.z; Bs[nb][kB + 7][lrB] = bv1.w;
            __syncthreads();
            buf = nb;
        }
    }

    #pragma unroll
    for (int i = 0; i < 4; i++) {
        float2 p0 = unpack2(acc[i][0]);
        float2 p1 = unpack2(acc[i][1]);
        *(float4*)&Out[(r0 + ty * 4 + i) * Hc + h0 + tx * 4] =
            make_float4(p0.x, p0.y, p1.x, p1.y);
    }
}

// ---------------------------------------------------------------------------
// Kernel 2: GEMM-shaped tanh-score (MUFU-bound, at its floor — unchanged).
// S[b,y,l] = sum_h vm[h] * tanh(Xp[b,l,h] - Yp[b,y,h])
// ---------------------------------------------------------------------------
__global__ __launch_bounds__(256) void score_tile_kernel(const float* __restrict__ vm)
{
    const int b  = blockIdx.z;
    const int y0 = blockIdx.y * 64;
    const int l0 = blockIdx.x * 64;

    __shared__ float Ys[16][68];
    __shared__ float Xs[16][68];
    __shared__ float Vs[Hc];

    const int tid = threadIdx.x;
    for (int i = tid; i < Hc; i += 256) Vs[i] = vm[i];

    const int lrow = tid >> 2;
    const int f4   = (tid & 3) * 4;
    const int tx   = tid & 15;
    const int ty   = tid >> 4;

    const float* Yb = g_Yp + (b * LYc + y0) * Hc;
    const float* Xb = g_Xp + (b * LXc + l0) * Hc;

    float acc[4][4] = {};

    for (int k0 = 0; k0 < Hc; k0 += 16) {
        float4 av = *(const float4*)&Yb[lrow * Hc + k0 + f4];
        float4 bv = *(const float4*)&Xb[lrow * Hc + k0 + f4];
        __syncthreads();
        Ys[f4 + 0][lrow] = av.x; Ys[f4 + 1][lrow] = av.y;
        Ys[f4 + 2][lrow] = av.z; Ys[f4 + 3][lrow] = av.w;
        Xs[f4 + 0][lrow] = bv.x; Xs[f4 + 1][lrow] = bv.y;
        Xs[f4 + 2][lrow] = bv.z; Xs[f4 + 3][lrow] = bv.w;
        __syncthreads();

        #pragma unroll
        for (int kk = 0; kk < 16; kk++) {
            const float v = Vs[k0 + kk];
            float4 yv = *(const float4*)&Ys[kk][ty * 4];
            float4 xv = *(const float4*)&Xs[kk][tx * 4];
            float t00 = tanh_fast(xv.x - yv.x);
            float t01 = tanh_fast(xv.y - yv.x);
            float t02 = tanh_fast(xv.z - yv.x);
            float t03 = tanh_fast(xv.w - yv.x);
            float t10 = tanh_fast(xv.x - yv.y);
            float t11 = tanh_fast(xv.y - yv.y);
            float t12 = tanh_fast(xv.z - yv.y);
            float t13 = tanh_fast(xv.w - yv.y);
            float t20 = tanh_fast(xv.x - yv.z);
            float t21 = tanh_fast(xv.y - yv.z);
            float t22 = tanh_fast(xv.z - yv.z);
            float t23 = tanh_fast(xv.w - yv.z);
            float t30 = tanh_fast(xv.x - yv.w);
            float t31 = tanh_fast(xv.y - yv.w);
            float t32 = tanh_fast(xv.z - yv.w);
            float t33 = tanh_fast(xv.w - yv.w);
            acc[0][0] = fmaf(v, t00, acc[0][0]);
            acc[0][1] = fmaf(v, t01, acc[0][1]);
            acc[0][2] = fmaf(v, t02, acc[0][2]);
            acc[0][3] = fmaf(v, t03, acc[0][3]);
            acc[1][0] = fmaf(v, t10, acc[1][0]);
            acc[1][1] = fmaf(v, t11, acc[1][1]);
            acc[1][2] = fmaf(v, t12, acc[1][2]);
            acc[1][3] = fmaf(v, t13, acc[1][3]);
            acc[2][0] = fmaf(v, t20, acc[2][0]);
            acc[2][1] = fmaf(v, t21, acc[2][1]);
            acc[2][2] = fmaf(v, t22, acc[2][2]);
            acc[2][3] = fmaf(v, t23, acc[2][3]);
            acc[3][0] = fmaf(v, t30, acc[3][0]);
            acc[3][1] = fmaf(v, t31, acc[3][1]);
            acc[3][2] = fmaf(v, t32, acc[3][2]);
            acc[3][3] = fmaf(v, t33, acc[3][3]);
        }
    }

    float* Sb = g_S + (b * LYc + y0) * LXc + l0;
    #pragma unroll
    for (int i = 0; i < 4; i++) {
        float4 st = make_float4(acc[i][0], acc[i][1], acc[i][2], acc[i][3]);
        *(float4*)&Sb[(ty * 4 + i) * LXc + tx * 4] = st;
    }
}

// ---------------------------------------------------------------------------
// Kernel 3a: softmax over l, in place on g_S. Warp per row.
// ---------------------------------------------------------------------------
__global__ __launch_bounds__(256) void softmax_kernel()
{
    const int b    = blockIdx.y;
    const int y    = blockIdx.x * 8 + (threadIdx.x >> 5);
    const int lane = threadIdx.x & 31;

    float* Srow = g_S + (b * LYc + y) * LXc;
    float v[12];
    float mx = -1e30f;
    #pragma unroll
    for (int j = 0; j < 12; j++) {
        v[j] = Srow[lane + 32 * j];
        mx = fmaxf(mx, v[j]);
    }
    #pragma unroll
    for (int o = 16; o; o >>= 1)
        mx = fmaxf(mx, __shfl_xor_sync(0xffffffffu, mx, o));
    float sum = 0.f;
    #pragma unroll
    for (int j = 0; j < 12; j++) {
        v[j] = ex2_fast((v[j] - mx) * 1.4426950408889634f);
        sum += v[j];
    }
    #pragma unroll
    for (int o = 16; o; o >>= 1)
        sum += __shfl_xor_sync(0xffffffffu, sum, o);
    float inv = 1.0f / sum;
    #pragma unroll
    for (int j = 0; j < 12; j++)
        Srow[lane + 32 * j] = v[j] * inv;
}

// ---------------------------------------------------------------------------
// Kernel 3b: qtm[b,y,f] = sum_l A[b,y,l] * x[b,l,f]
// Per-batch GEMM M=384(y), N=512(f), K=384(l).  32x64 tile, 128 threads,
// BK=16 double-buffered, FFMA2.  grid (8, 12, 4) = 384 blocks.
// Padding: A rows 36 floats, X rows 68 floats (both 16B-aligned strides).
// ---------------------------------------------------------------------------
__global__ __launch_bounds__(128) void outgemm_kernel(
    const float* __restrict__ x, float* __restrict__ out)
{
    const int b  = blockIdx.z;
    const int f0 = blockIdx.x * 64;
    const int y0 = blockIdx.y * 32;

    __shared__ float As[2][16][36];   // [k(l)][y(32)]
    __shared__ float Xs[2][16][68];   // [k(l)][f(64)]

    const int tid = threadIdx.x;

    const int lrA = tid >> 2;           // 0..31  (y row for A load)
    const int kA  = (tid & 3) * 4;      // l sub for A load
    const int lX  = tid >> 3;           // 0..15  (l row for X load)
    const int fX  = (tid & 7) * 8;      // f sub for X load (8 floats)

    const int tx = tid & 15;            // f micro-col
    const int ty = tid >> 4;            // y micro-row

    const float* pA = g_S + (b * LYc + y0 + lrA) * LXc + kA;
    const float* pX = x + b * LXc * Fc + lX * Fc + f0 + fX;

    ull acc[4][2] = {};

    {
        float4 av  = *(const float4*)pA;
        float4 xv0 = *(const float4*)pX;
        float4 xv1 = *(const float4*)(pX + 4);
        As[0][kA + 0][lrA] = av.x; As[0][kA + 1][lrA] = av.y;
        As[0][kA + 2][lrA] = av.z; As[0][kA + 3][lrA] = av.w;
        *(float4*)&Xs[0][lX][fX]     = xv0;
        *(float4*)&Xs[0][lX][fX + 4] = xv1;
    }
    __syncthreads();

    int buf = 0;
    for (int k0 = 16; k0 <= LXc; k0 += 16) {
        float4 av, xv0, xv1;
        if (k0 < LXc) {
            av  = *(const float4*)(pA + k0);
            xv0 = *(const float4*)(pX + k0 * Fc);
            xv1 = *(const float4*)(pX + k0 * Fc + 4);
        }
        #pragma unroll
        for (int kk = 0; kk < 16; kk++) {
            float4 a = *(const float4*)&As[buf][kk][ty * 4];
            ull b01  = *(const ull*)&Xs[buf][kk][tx * 4];
            ull b23  = *(const ull*)&Xs[buf][kk][tx * 4 + 2];
            ull ax = pack2(a.x, a.x), ay = pack2(a.y, a.y);
            ull az = pack2(a.z, a.z), aw = pack2(a.w, a.w);
            acc[0][0] = fma2(ax, b01, acc[0][0]);
            acc[0][1] = fma2(ax, b23, acc[0][1]);
            acc[1][0] = fma2(ay, b01, acc[1][0]);
            acc[1][1] = fma2(ay, b23, acc[1][1]);
            acc[2][0] = fma2(az, b01, acc[2][0]);
            acc[2][1] = fma2(az, b23, acc[2][1]);
            acc[3][0] = fma2(aw, b01, acc[3][0]);
            acc[3][1] = fma2(aw, b23, acc[3][1]);
        }
        if (k0 < LXc) {
            int nb = buf ^ 1;
            As[nb][kA + 0][lrA] = av.x; As[nb][kA + 1][lrA] = av.y;
            As[nb][kA + 2][lrA] = av.z; As[nb][kA + 3][lrA] = av.w;
            *(float4*)&Xs[nb][lX][fX]     = xv0;
            *(float4*)&Xs[nb][lX][fX + 4] = xv1;
            __syncthreads();
            buf = nb;
        }
    }

    #pragma unroll
    for (int i = 0; i < 4; i++) {
        float2 p0 = unpack2(acc[i][0]);
        float2 p1 = unpack2(acc[i][1]);
        *(float4*)&out[(b * LYc + y0 + ty * 4 + i) * Fc + f0 + tx * 4] =
            make_float4(p0.x, p0.y, p1.x, p1.y);
    }
}

// ---------------------------------------------------------------------------
extern "C" void kernel_launch(void* const* d_in, const int* in_sizes, int n_in,
                              void* d_out, int out_size)
{
    const float* x  = (const float*)d_in[0];
    const float* y  = (const float*)d_in[1];
    const float* Wm = (const float*)d_in[2];
    const float* vm = (const float*)d_in[3];
    float* out = (float*)d_out;

    proj_kernel      <<<dim3(LXc * Bc / 32, Hc / 64, 2), 128>>>(x, y, Wm);
    score_tile_kernel<<<dim3(LXc / 64, LYc / 64, Bc), 256>>>(vm);
    softmax_kernel   <<<dim3(LYc / 8, Bc), 256>>>();
    outgemm_kernel   <<<dim3(Fc / 64, LYc / 32, Bc), 128>>>(x, out);
}